// round 4
// baseline (speedup 1.0000x reference)
#include <cuda_runtime.h>
#include <math.h>
#include <stdint.h>
#include <string.h>

// B=32, T=1024, D_IN=80, enc: 80->512->512->256 (ReLU), F=768, 4H=1024, H=256

// ------------------------- device scratch -------------------------
__device__ float d_buf0[32768 * 512];
__device__ float d_buf1[32768 * 512];
__device__ float d_h[32768 * 256];
__device__ float d_d1[32768 * 256];
__device__ float d_feat[32768 * 768];
__device__ float d_Z[32768 * 2048];        // [row=b*1024+t][2048]: cols 0..1023 fwd, 1024..2047 bwd
__device__ float d_biascat[2048];
__device__ float d_Hbuf[2][2][32][256];    // [parity][dir][b][k]
__device__ float d_Hout[2][1024][256][32]; // [dir][t][k][b]
__device__ int d_order[32];
__device__ int d_lens[32];
__device__ unsigned d_ctr;
// pre-converted bf16 hi/lo weights
__device__ uint16_t d_Wch[2048 * 768], d_Wcl[2048 * 768];
__device__ uint16_t d_W1h[512 * 512], d_W1l[512 * 512];
__device__ uint16_t d_W2h[256 * 512], d_W2l[256 * 512];

// ------------------------- helpers -------------------------
__device__ __forceinline__ uint32_t s2u(const void* p) {
    uint32_t a;
    asm("{ .reg .u64 t; cvta.to.shared.u64 t, %1; cvt.u32.u64 %0, t; }" : "=r"(a) : "l"(p));
    return a;
}
__device__ __forceinline__ uint32_t cvt2bf(float lo, float hi) {
    uint32_t r;
    asm("cvt.rn.satfinite.bf16x2.f32 %0, %1, %2;" : "=r"(r) : "f"(hi), "f"(lo));
    return r;
}
__device__ __forceinline__ void ldsm4(uint32_t* r, uint32_t addr) {
    asm volatile("ldmatrix.sync.aligned.m8n8.x4.shared.b16 {%0,%1,%2,%3}, [%4];"
                 : "=r"(r[0]), "=r"(r[1]), "=r"(r[2]), "=r"(r[3]) : "r"(addr));
}
__device__ __forceinline__ void mma16816(float* c, const uint32_t* a, uint32_t b0, uint32_t b1) {
    asm volatile(
        "mma.sync.aligned.m16n8k16.row.col.f32.bf16.bf16.f32 "
        "{%0,%1,%2,%3}, {%4,%5,%6,%7}, {%8,%9}, {%0,%1,%2,%3};"
        : "+f"(c[0]), "+f"(c[1]), "+f"(c[2]), "+f"(c[3])
        : "r"(a[0]), "r"(a[1]), "r"(a[2]), "r"(a[3]), "r"(b0), "r"(b1));
}
__device__ __forceinline__ void fma2(unsigned long long& d, unsigned long long a, unsigned long long b) {
    asm("fma.rn.f32x2 %0, %1, %2, %0;" : "+l"(d) : "l"(a), "l"(b));
}
__device__ __forceinline__ float psum(unsigned long long v) {
    float2 f;
    memcpy(&f, &v, 8);
    return f.x + f.y;
}
#define SWZB(row, c) ((((uint32_t)(row)) << 6) + ((((uint32_t)(c) ^ (((uint32_t)(row) >> 1) & 3))) << 4))

__device__ __forceinline__ void st_unit(char* hi, char* lo, int row, int c, float4 v0, float4 v1) {
    float p0[4] = {v0.x, v0.z, v1.x, v1.z};
    float p1[4] = {v0.y, v0.w, v1.y, v1.w};
    uint32_t h[4], l[4];
#pragma unroll
    for (int j = 0; j < 4; ++j) {
        uint32_t ph = cvt2bf(p0[j], p1[j]);
        float hx = __uint_as_float(ph << 16);
        float hy = __uint_as_float(ph & 0xffff0000u);
        uint32_t pl = cvt2bf(p0[j] - hx, p1[j] - hy);
        h[j] = ph; l[j] = pl;
    }
    uint32_t off = SWZB(row, c);
    *(uint4*)(hi + off) = make_uint4(h[0], h[1], h[2], h[3]);
    *(uint4*)(lo + off) = make_uint4(l[0], l[1], l[2], l[3]);
}

// ------------------------- order (stable argsort desc) -------------------------
__global__ void compute_order_k(const int* __restrict__ xlen) {
    if (threadIdx.x == 0) {
        unsigned used = 0;
        for (int p = 0; p < 32; ++p) {
            int best = -1, bl = -2147483647;
            for (int j = 0; j < 32; ++j) {
                if (used & (1u << j)) continue;
                int L = xlen[j];
                if (L > bl) { bl = L; best = j; }
            }
            used |= (1u << best);
            d_order[p] = best;
            d_lens[p] = bl;
        }
        d_ctr = 0u;
    }
}

__global__ void bias_k(const float* __restrict__ bihf, const float* __restrict__ bhhf,
                       const float* __restrict__ bihb, const float* __restrict__ bhhb) {
    int j = blockIdx.x * 1024 + threadIdx.x;
    if (j < 1024) d_biascat[j] = bihf[j] + bhhf[j];
    else d_biascat[j] = bihb[j - 1024] + bhhb[j - 1024];
}

// weight fp32 -> bf16 hi/lo pairs
__global__ void convw_k(const float* __restrict__ src, uint16_t* __restrict__ dh,
                        uint16_t* __restrict__ dl, int npairs) {
    int i = blockIdx.x * 256 + threadIdx.x;
    if (i >= npairs) return;
    float2 v = ((const float2*)src)[i];
    uint32_t ph = cvt2bf(v.x, v.y);
    float hx = __uint_as_float(ph << 16);
    float hy = __uint_as_float(ph & 0xffff0000u);
    uint32_t pl = cvt2bf(v.x - hx, v.y - hy);
    ((uint32_t*)dh)[i] = ph;
    ((uint32_t*)dl)[i] = pl;
}

// ------------------------- fp32 GEMM (only for K=80 layer 0) -------------------------
__global__ void __launch_bounds__(256) gemm_relu_k(
    const float* __restrict__ A, const float* __restrict__ W,
    const float* __restrict__ bias, float* __restrict__ C,
    int M, int N, int K) {
    __shared__ float As[8][132];
    __shared__ float Ws[8][132];
    const int tid = threadIdx.x;
    const int n0 = blockIdx.x * 128, m0 = blockIdx.y * 128;
    const int lm = tid >> 1, lq = (tid & 1) * 4;
    const float* arow = A + (size_t)(m0 + lm) * K + lq;
    const float* wrow = W + (size_t)(n0 + lm) * K + lq;
    const int tx = tid & 15, ty = tid >> 4;
    float acc[8][8];
#pragma unroll
    for (int i = 0; i < 8; i++)
#pragma unroll
        for (int j = 0; j < 8; j++) acc[i][j] = 0.f;

    for (int k0 = 0; k0 < K; k0 += 8) {
        float4 av = *(const float4*)(arow + k0);
        float4 wv = *(const float4*)(wrow + k0);
        __syncthreads();
        As[lq + 0][lm] = av.x; As[lq + 1][lm] = av.y;
        As[lq + 2][lm] = av.z; As[lq + 3][lm] = av.w;
        Ws[lq + 0][lm] = wv.x; Ws[lq + 1][lm] = wv.y;
        Ws[lq + 2][lm] = wv.z; Ws[lq + 3][lm] = wv.w;
        __syncthreads();
#pragma unroll
        for (int k = 0; k < 8; k++) {
            float a[8], b[8];
            *(float4*)(a) = *(const float4*)&As[k][ty * 8];
            *(float4*)(a + 4) = *(const float4*)&As[k][ty * 8 + 4];
            *(float4*)(b) = *(const float4*)&Ws[k][tx * 8];
            *(float4*)(b + 4) = *(const float4*)&Ws[k][tx * 8 + 4];
#pragma unroll
            for (int i = 0; i < 8; i++)
#pragma unroll
                for (int j = 0; j < 8; j++) acc[i][j] += a[i] * b[j];
        }
    }
    float bs[8];
    *(float4*)bs = *(const float4*)&bias[n0 + tx * 8];
    *(float4*)(bs + 4) = *(const float4*)&bias[n0 + tx * 8 + 4];
#pragma unroll
    for (int i = 0; i < 8; i++) {
        float* crow = C + (size_t)(m0 + ty * 8 + i) * N + n0 + tx * 8;
        float4 v0, v1;
        v0.x = fmaxf(acc[i][0] + bs[0], 0.f);
        v0.y = fmaxf(acc[i][1] + bs[1], 0.f);
        v0.z = fmaxf(acc[i][2] + bs[2], 0.f);
        v0.w = fmaxf(acc[i][3] + bs[3], 0.f);
        v1.x = fmaxf(acc[i][4] + bs[4], 0.f);
        v1.y = fmaxf(acc[i][5] + bs[5], 0.f);
        v1.z = fmaxf(acc[i][6] + bs[6], 0.f);
        v1.w = fmaxf(acc[i][7] + bs[7], 0.f);
        *(float4*)crow = v0;
        *(float4*)(crow + 4) = v1;
    }
}

// ------------------------- HMMA split-bf16 GEMM (pre-converted B) -------------------------
// C[M][N] = (relu)(A[M][K] @ B[N][K]^T + bias); B given as bf16 hi/lo arrays.
template <int RELU>
__global__ void __launch_bounds__(256) gemm_mma_k(
    const float* __restrict__ A, const uint16_t* __restrict__ Bhi,
    const uint16_t* __restrict__ Blo,
    const float* __restrict__ bias, float* __restrict__ C,
    int K, int ldo) {
    extern __shared__ char smc[];
    const int tid = threadIdx.x, lane = tid & 31, wid = tid >> 5;
    const int wm = wid >> 2, wn = wid & 3;
    const int n0 = blockIdx.x * 128, m0 = blockIdx.y * 128;
    const int NCH = K >> 5;
    const uint32_t sbase = s2u(smc);
    float* sBias = (float*)(smc + 65536);
    if (tid < 128) sBias[tid] = bias[n0 + tid];

    const int ra = tid >> 2, ca = tid & 3;
    const float* Ap0 = A + (size_t)(m0 + ra) * K + ca * 8;
    const float* Ap1 = A + (size_t)(m0 + 64 + ra) * K + ca * 8;
    const int ldb = K >> 3;
    const uint4* Bh0 = (const uint4*)Bhi + (size_t)(n0 + ra) * ldb + ca;
    const uint4* Bl0 = (const uint4*)Blo + (size_t)(n0 + ra) * ldb + ca;
    const uint4* Bh1 = (const uint4*)Bhi + (size_t)(n0 + 64 + ra) * ldb + ca;
    const uint4* Bl1 = (const uint4*)Blo + (size_t)(n0 + 64 + ra) * ldb + ca;

    float acc[4][4][4];
#pragma unroll
    for (int mi = 0; mi < 4; mi++)
#pragma unroll
        for (int j = 0; j < 4; j++)
#pragma unroll
            for (int q = 0; q < 4; q++) acc[mi][j][q] = 0.f;

    // stage chunk 0 into buf 0
    {
        char* base = smc;
        st_unit(base, base + 8192, ra, ca, *(const float4*)Ap0, *(const float4*)(Ap0 + 4));
        st_unit(base, base + 8192, 64 + ra, ca, *(const float4*)Ap1, *(const float4*)(Ap1 + 4));
        uint32_t o0 = SWZB(ra, ca), o1 = SWZB(64 + ra, ca);
        *(uint4*)(base + 16384 + o0) = *Bh0;
        *(uint4*)(base + 24576 + o0) = *Bl0;
        *(uint4*)(base + 16384 + o1) = *Bh1;
        *(uint4*)(base + 24576 + o1) = *Bl1;
    }
    __syncthreads();

    for (int i = 0; i < NCH; ++i) {
        float4 pa0, pa1, pa2, pa3;
        uint4 pb0, pb1, pb2, pb3;
        const bool more = (i + 1 < NCH);
        if (more) {
            const int kc = (i + 1) << 5;
            const int ku = (i + 1) << 2;
            pa0 = *(const float4*)(Ap0 + kc); pa1 = *(const float4*)(Ap0 + kc + 4);
            pa2 = *(const float4*)(Ap1 + kc); pa3 = *(const float4*)(Ap1 + kc + 4);
            pb0 = Bh0[ku]; pb1 = Bl0[ku];
            pb2 = Bh1[ku]; pb3 = Bl1[ku];
        }
        const uint32_t ab = sbase + (i & 1) * 32768;
        const uint32_t bb = ab + 16384;
#pragma unroll
        for (int ks = 0; ks < 2; ++ks) {
            const int r = lane & 15;
            const int cu = (ks << 1) + (lane >> 4);
            uint32_t ah[4][4], al[4][4], bh[2][4], bl[2][4];
#pragma unroll
            for (int mi = 0; mi < 4; ++mi) {
                uint32_t off = SWZB(wm * 64 + mi * 16 + r, cu);
                ldsm4(ah[mi], ab + off);
                ldsm4(al[mi], ab + 8192 + off);
            }
#pragma unroll
            for (int ni = 0; ni < 2; ++ni) {
                uint32_t off = SWZB(wn * 32 + ni * 16 + r, cu);
                ldsm4(bh[ni], bb + off);
                ldsm4(bl[ni], bb + 8192 + off);
            }
#pragma unroll
            for (int mi = 0; mi < 4; ++mi)
#pragma unroll
                for (int j = 0; j < 4; ++j) {
                    const int ni = j >> 1, s = j & 1;
                    mma16816(acc[mi][j], ah[mi], bh[ni][s], bh[ni][s + 2]);
                    mma16816(acc[mi][j], al[mi], bh[ni][s], bh[ni][s + 2]);
                    mma16816(acc[mi][j], ah[mi], bl[ni][s], bl[ni][s + 2]);
                }
        }
        if (more) {
            char* base = smc + ((i + 1) & 1) * 32768;
            st_unit(base, base + 8192, ra, ca, pa0, pa1);
            st_unit(base, base + 8192, 64 + ra, ca, pa2, pa3);
            uint32_t o0 = SWZB(ra, ca), o1 = SWZB(64 + ra, ca);
            *(uint4*)(base + 16384 + o0) = pb0;
            *(uint4*)(base + 24576 + o0) = pb1;
            *(uint4*)(base + 16384 + o1) = pb2;
            *(uint4*)(base + 24576 + o1) = pb3;
        }
        __syncthreads();
    }

#pragma unroll
    for (int mi = 0; mi < 4; ++mi)
#pragma unroll
        for (int j = 0; j < 4; ++j) {
            const int row = m0 + wm * 64 + mi * 16 + (lane >> 2);
            const int colL = wn * 32 + j * 8 + (lane & 3) * 2;
            const float b0v = sBias[colL], b1v = sBias[colL + 1];
            float x0 = acc[mi][j][0] + b0v, x1 = acc[mi][j][1] + b1v;
            float x2 = acc[mi][j][2] + b0v, x3 = acc[mi][j][3] + b1v;
            if (RELU) {
                x0 = fmaxf(x0, 0.f); x1 = fmaxf(x1, 0.f);
                x2 = fmaxf(x2, 0.f); x3 = fmaxf(x3, 0.f);
            }
            *(float2*)(C + (size_t)row * ldo + n0 + colL) = make_float2(x0, x1);
            *(float2*)(C + (size_t)(row + 8) * ldo + n0 + colL) = make_float2(x2, x3);
        }
}

// ------------------------- deltas (WIN=2, edge replicate) -------------------------
__global__ void deltas_k() {
    int idx = blockIdx.x * 256 + threadIdx.x;
    if (idx >= 32 * 1024 * 64) return;
    int c4 = idx & 63, t = (idx >> 6) & 1023, b = idx >> 16;
    const float4* h4 = (const float4*)d_h;
    size_t base = (size_t)b * 65536;
    int tp1 = min(t + 1, 1023), tm1 = max(t - 1, 0);
    int tp2 = min(t + 2, 1023), tm2 = max(t - 2, 0);
    float4 a = h4[base + (size_t)tp1 * 64 + c4];
    float4 bb = h4[base + (size_t)tm1 * 64 + c4];
    float4 c = h4[base + (size_t)tp2 * 64 + c4];
    float4 d = h4[base + (size_t)tm2 * 64 + c4];
    float4 z;
    z.x = (a.x - bb.x) * 0.5f + (c.x - d.x) * 0.25f;
    z.y = (a.y - bb.y) * 0.5f + (c.y - d.y) * 0.25f;
    z.z = (a.z - bb.z) * 0.5f + (c.z - d.z) * 0.25f;
    z.w = (a.w - bb.w) * 0.5f + (c.w - d.w) * 0.25f;
    ((float4*)d_d1)[base + (size_t)t * 64 + c4] = z;
}

// ------------------------- feat assembly (sorted) -------------------------
__global__ void feat_k() {
    int idx = blockIdx.x * 256 + threadIdx.x;
    if (idx >= 32 * 1024 * 64) return;
    int c4 = idx & 63, t = (idx >> 6) & 1023, sb = idx >> 16;
    int b = d_order[sb];
    const float4* h4 = (const float4*)d_h;
    const float4* d14 = (const float4*)d_d1;
    float4* f4 = (float4*)d_feat;
    size_t base = (size_t)b * 65536;
    size_t srow = base + (size_t)t * 64 + c4;
    float4 hv = h4[srow];
    float4 d1v = d14[srow];
    int tp1 = min(t + 1, 1023), tm1 = max(t - 1, 0);
    int tp2 = min(t + 2, 1023), tm2 = max(t - 2, 0);
    float4 a = d14[base + (size_t)tp1 * 64 + c4];
    float4 bb = d14[base + (size_t)tm1 * 64 + c4];
    float4 c = d14[base + (size_t)tp2 * 64 + c4];
    float4 d = d14[base + (size_t)tm2 * 64 + c4];
    float4 d2v;
    d2v.x = (a.x - bb.x) * 0.5f + (c.x - d.x) * 0.25f;
    d2v.y = (a.y - bb.y) * 0.5f + (c.y - d.y) * 0.25f;
    d2v.z = (a.z - bb.z) * 0.5f + (c.z - d.z) * 0.25f;
    d2v.w = (a.w - bb.w) * 0.5f + (c.w - d.w) * 0.25f;
    size_t obase = ((size_t)sb * 1024 + t) * 192;
    f4[obase + c4] = hv;
    f4[obase + 64 + c4] = d1v;
    f4[obase + 128 + c4] = d2v;
}

// ------------------------- persistent bidirectional LSTM recurrence -------------------------
// 128 CTAs: dir = cta>>6, slice = cta&63 (owns h units slice*4..+3 -> 16 gate rows).
// Warps 0-3 compute dots (1 r x 4 b each, f32x2 FMA); warps 4-7 prefetch Z.
__global__ void __launch_bounds__(256, 1) lstm_rec_k(
    const float* __restrict__ Whh_f, const float* __restrict__ Whh_b,
    const float* __restrict__ h0, const float* __restrict__ c0) {
    extern __shared__ float sm[];
    float* sW = sm;                   // [r][k] stride 260
    float* sH = sm + 4160;            // [b][k] stride 260
    float* sG = sm + 4160 + 8320;     // [r][b] stride 33
    float* sZ0 = sG + 528;            // [r][b] stride 33
    float* sZ1 = sZ0 + 528;
    const int tid = threadIdx.x;
    const int cta = blockIdx.x;
    const int dir = cta >> 6;
    const int slice = cta & 63;
    const float* Whh = dir ? Whh_b : Whh_f;

    // stage Whh slice: local r = gate*4+unit -> global row gate*256 + slice*4 + unit
    for (int i = tid; i < 4096; i += 256) {
        int rr = i >> 8, k = i & 255;
        int j = ((rr >> 2) << 8) + (slice << 2) + (rr & 3);
        sW[rr * 260 + k] = Whh[(size_t)j * 256 + k];
    }

    const int uq = tid >> 5, ub = tid & 31;
    const int kidx = (slice << 2) + uq;
    float creg = 0.f;
    if (tid < 128) {
        creg = c0[(dir * 32 + ub) * 256 + kidx];
        d_Hbuf[0][dir][ub][kidx] = h0[(dir * 32 + ub) * 256 + kidx];
    }

    // service thread Z setup + t=0 Z prefetch
    size_t Zoff[4];
    int si[4], Lz[4];
    if (tid >= 128) {
        int s = tid - 128;
#pragma unroll
        for (int v = 0; v < 4; ++v) {
            int idx = s + (v << 7);
            int zr = idx >> 5, zb = idx & 31;
            int jg = ((zr >> 2) << 8) + (slice << 2) + (zr & 3);
            Zoff[v] = ((size_t)zb << 11) * 1024 + dir * 1024 + jg;
            si[v] = zr * 33 + zb;
            Lz[v] = d_lens[zb];
        }
#pragma unroll
        for (int v = 0; v < 4; ++v) {
            int tt = dir ? max(Lz[v] - 1, 0) : 0;
            sZ0[si[v]] = __ldg(d_Z + Zoff[v] + ((size_t)tt << 11));
        }
    }
    __syncthreads();
    unsigned target = 128u;
    if (tid == 0) {
        asm volatile("red.release.gpu.global.add.u32 [%0], %1;" :: "l"(&d_ctr), "r"(1u) : "memory");
        unsigned v;
        do {
            asm volatile("ld.acquire.gpu.global.u32 %0, [%1];" : "=r"(v) : "l"(&d_ctr) : "memory");
        } while (v < target);
    }
    __syncthreads();

    const int wid = tid >> 5, lane = tid & 31;
    const int r = (wid << 2) + (lane >> 3);  // compute warps only (wid<4)
    const int bg = lane & 7;

    for (int t = 0; t < 1024; ++t) {
        // all threads: stage h_{t-1} global -> smem (layouts match, no transpose)
        {
            const float4* src = (const float4*)&d_Hbuf[t & 1][dir][0][0];
#pragma unroll
            for (int q = 0; q < 8; ++q) {
                int u = q * 256 + tid;
                float4 v = __ldcg(src + u);
                int b = u >> 6, ku = (u & 63) << 2;
                *(float4*)&sH[b * 260 + ku] = v;
            }
        }
        __syncthreads();  // sH ready; sZ[t&1] ready (prev iter / t0)
        const float* zcur = (t & 1) ? sZ1 : sZ0;
        if (tid < 128) {
            const float* wr = sW + r * 260;
            const float* h0p = sH + bg * 260;
            const float* h1p = sH + (bg + 8) * 260;
            const float* h2p = sH + (bg + 16) * 260;
            const float* h3p = sH + (bg + 24) * 260;
            unsigned long long a0 = 0ull, a1 = 0ull, a2 = 0ull, a3 = 0ull;
#pragma unroll 8
            for (int k = 0; k < 256; k += 4) {
                ulonglong2 w2 = *(const ulonglong2*)(wr + k);
                ulonglong2 x0 = *(const ulonglong2*)(h0p + k);
                ulonglong2 x1 = *(const ulonglong2*)(h1p + k);
                ulonglong2 x2 = *(const ulonglong2*)(h2p + k);
                ulonglong2 x3 = *(const ulonglong2*)(h3p + k);
                fma2(a0, x0.x, w2.x); fma2(a0, x0.y, w2.y);
                fma2(a1, x1.x, w2.x); fma2(a1, x1.y, w2.y);
                fma2(a2, x2.x, w2.x); fma2(a2, x2.y, w2.y);
                fma2(a3, x3.x, w2.x); fma2(a3, x3.y, w2.y);
            }
            const float* zc = zcur + r * 33;
            float* gc = sG + r * 33;
            gc[bg] = psum(a0) + zc[bg];
            gc[bg + 8] = psum(a1) + zc[bg + 8];
            gc[bg + 16] = psum(a2) + zc[bg + 16];
            gc[bg + 24] = psum(a3) + zc[bg + 24];
        } else if (t + 1 < 1024) {
            float* dst = ((t + 1) & 1) ? sZ1 : sZ0;
#pragma unroll
            for (int v = 0; v < 4; ++v) {
                int tt = dir ? max(Lz[v] - 2 - t, 0) : (t + 1);
                dst[si[v]] = __ldg(d_Z + Zoff[v] + ((size_t)tt << 11));
            }
        }
        __syncthreads();  // sG ready
        if (tid < 128) {
            float ig = sG[uq * 33 + ub];
            float fg = sG[(4 + uq) * 33 + ub];
            float gg = sG[(8 + uq) * 33 + ub];
            float og = sG[(12 + uq) * 33 + ub];
            float is = 1.f / (1.f + expf(-ig));
            float fs = 1.f / (1.f + expf(-fg));
            float os = 1.f / (1.f + expf(-og));
            creg = fs * creg + is * tanhf(gg);
            float hv = os * tanhf(creg);
            d_Hbuf[(t + 1) & 1][dir][ub][kidx] = hv;
            d_Hout[dir][t][kidx][ub] = hv;
        }
        __syncthreads();
        target += 128u;
        if (tid == 0) {
            asm volatile("red.release.gpu.global.add.u32 [%0], %1;" :: "l"(&d_ctr), "r"(1u) : "memory");
            unsigned v;
            do {
                asm volatile("ld.acquire.gpu.global.u32 %0, [%1];" : "=r"(v) : "l"(&d_ctr) : "memory");
            } while (v < target);
        }
        __syncthreads();
    }
}

// ------------------------- output assembly -------------------------
__global__ void outk(float* __restrict__ out, int out_size) {
    int idx = blockIdx.x * 256 + threadIdx.x;
    if (idx >= out_size) return;
    if (idx < 16777216) {
        int j = idx & 511;
        int t = (idx >> 9) & 1023;
        int sb = idx >> 19;
        int L = d_lens[sb];
        float v = 0.f;
        if (t < L) {
            if (j < 256) v = d_Hout[0][t][j][sb];
            else v = d_Hout[1][L - 1 - t][j - 256][sb];
        }
        out[idx] = v;
    } else {
        int k = idx - 16777216;
        if (k < 32) out[idx] = (float)d_order[k];
        else out[idx] = 0.f;
    }
}

// ------------------------- launch -------------------------
extern "C" void kernel_launch(void* const* d_in, const int* in_sizes, int n_in,
                              void* d_out, int out_size) {
    const float* x = (const float*)d_in[0];
    const int* xlen = (const int*)d_in[1];
    const float* W0 = (const float*)d_in[2];
    const float* b0 = (const float*)d_in[3];
    const float* W1 = (const float*)d_in[4];
    const float* b1 = (const float*)d_in[5];
    const float* W2 = (const float*)d_in[6];
    const float* b2 = (const float*)d_in[7];
    const float* Wih_f = (const float*)d_in[8];
    const float* Whh_f = (const float*)d_in[9];
    const float* bih_f = (const float*)d_in[10];
    const float* bhh_f = (const float*)d_in[11];
    const float* Wih_b = (const float*)d_in[12];
    const float* Whh_b = (const float*)d_in[13];
    const float* bih_b = (const float*)d_in[14];
    const float* bhh_b = (const float*)d_in[15];
    const float* h0 = (const float*)d_in[16];
    const float* c0 = (const float*)d_in[17];
    float* out = (float*)d_out;

    void *p_buf0, *p_buf1, *p_h, *p_feat, *p_Z, *p_bias;
    void *p_wch, *p_wcl, *p_w1h, *p_w1l, *p_w2h, *p_w2l;
    cudaGetSymbolAddress(&p_buf0, d_buf0);
    cudaGetSymbolAddress(&p_buf1, d_buf1);
    cudaGetSymbolAddress(&p_h, d_h);
    cudaGetSymbolAddress(&p_feat, d_feat);
    cudaGetSymbolAddress(&p_Z, d_Z);
    cudaGetSymbolAddress(&p_bias, d_biascat);
    cudaGetSymbolAddress(&p_wch, d_Wch);
    cudaGetSymbolAddress(&p_wcl, d_Wcl);
    cudaGetSymbolAddress(&p_w1h, d_W1h);
    cudaGetSymbolAddress(&p_w1l, d_W1l);
    cudaGetSymbolAddress(&p_w2h, d_W2h);
    cudaGetSymbolAddress(&p_w2l, d_W2l);

    cudaFuncSetAttribute(gemm_mma_k<0>, cudaFuncAttributeMaxDynamicSharedMemorySize, 66048);
    cudaFuncSetAttribute(gemm_mma_k<1>, cudaFuncAttributeMaxDynamicSharedMemorySize, 66048);
    cudaFuncSetAttribute(lstm_rec_k, cudaFuncAttributeMaxDynamicSharedMemorySize, 60000);

    compute_order_k<<<1, 32>>>(xlen);
    bias_k<<<2, 1024>>>(bih_f, bhh_f, bih_b, bhh_b);

    // pre-convert static weights to bf16 hi/lo
    convw_k<<<(131072 + 255) / 256, 256>>>(W1, (uint16_t*)p_w1h, (uint16_t*)p_w1l, 131072);
    convw_k<<<(65536 + 255) / 256, 256>>>(W2, (uint16_t*)p_w2h, (uint16_t*)p_w2l, 65536);
    convw_k<<<(393216 + 255) / 256, 256>>>(Wih_f, (uint16_t*)p_wch, (uint16_t*)p_wcl, 393216);
    convw_k<<<(393216 + 255) / 256, 256>>>(
        Wih_b, (uint16_t*)p_wch + 1024 * 768, (uint16_t*)p_wcl + 1024 * 768, 393216);

    // encoder
    gemm_relu_k<<<dim3(4, 256), 256>>>(x, W0, b0, (float*)p_buf0, 32768, 512, 80);
    gemm_mma_k<1><<<dim3(4, 256), 256, 66048>>>(
        (const float*)p_buf0, (const uint16_t*)p_w1h, (const uint16_t*)p_w1l,
        b1, (float*)p_buf1, 512, 512);
    gemm_mma_k<1><<<dim3(2, 256), 256, 66048>>>(
        (const float*)p_buf1, (const uint16_t*)p_w2h, (const uint16_t*)p_w2l,
        b2, (float*)p_h, 512, 256);

    deltas_k<<<8192, 256>>>();
    feat_k<<<8192, 256>>>();

    // Z = feat @ [Wih_f ; Wih_b]^T + biascat  (both directions fused)
    gemm_mma_k<0><<<dim3(16, 256), 256, 66048>>>(
        (const float*)p_feat, (const uint16_t*)p_wch, (const uint16_t*)p_wcl,
        (const float*)p_bias, (float*)p_Z, 768, 2048);

    lstm_rec_k<<<128, 256, 60000>>>(Whh_f, Whh_b, h0, c0);

    outk<<<(out_size + 255) / 256, 256>>>(out, out_size);
}

// round 5
// speedup vs baseline: 1.3497x; 1.3497x over previous
#include <cuda_runtime.h>
#include <math.h>
#include <stdint.h>
#include <string.h>

// B=32, T=1024, D_IN=80, enc: 80->512->512->256 (ReLU), F=768, 4H=1024, H=256

// ------------------------- device scratch -------------------------
__device__ float d_buf0[32768 * 512];
__device__ float d_buf1[32768 * 512];
__device__ float d_h[32768 * 256];
__device__ float d_d1[32768 * 256];
__device__ float d_feat[32768 * 768];
__device__ float d_Z[32768 * 2048];        // [b][t][2048]: cols 0..1023 fwd, 1024..2047 bwd
__device__ float d_biascat[2048];
__device__ uint32_t d_Hc[2][2][32][256];   // [parity][dir][b][k] packed (bf16hi<<16)|bf16lo
__device__ float d_Hout[2][1024][256][32]; // [dir][t][k][b]
__device__ int d_order[32];
__device__ int d_lens[32];
__device__ unsigned d_ctr2[2];
// pre-converted bf16 hi/lo weights
__device__ uint16_t d_Wch[2048 * 768], d_Wcl[2048 * 768];
__device__ uint16_t d_W1h[512 * 512], d_W1l[512 * 512];
__device__ uint16_t d_W2h[256 * 512], d_W2l[256 * 512];

// ------------------------- helpers -------------------------
__device__ __forceinline__ uint32_t s2u(const void* p) {
    uint32_t a;
    asm("{ .reg .u64 t; cvta.to.shared.u64 t, %1; cvt.u32.u64 %0, t; }" : "=r"(a) : "l"(p));
    return a;
}
__device__ __forceinline__ uint32_t cvt2bf(float lo, float hi) {
    uint32_t r;
    asm("cvt.rn.satfinite.bf16x2.f32 %0, %1, %2;" : "=r"(r) : "f"(hi), "f"(lo));
    return r;
}
// pack fp32 -> (bf16hi<<16)|bf16lo
__device__ __forceinline__ uint32_t packhl(float v) {
    uint32_t u = cvt2bf(0.f, v);
    float resid = v - __uint_as_float(u & 0xffff0000u);
    return cvt2bf(resid, v);
}
__device__ __forceinline__ void ldsm4(uint32_t* r, uint32_t addr) {
    asm volatile("ldmatrix.sync.aligned.m8n8.x4.shared.b16 {%0,%1,%2,%3}, [%4];"
                 : "=r"(r[0]), "=r"(r[1]), "=r"(r[2]), "=r"(r[3]) : "r"(addr));
}
__device__ __forceinline__ void mma16816(float* c, const uint32_t* a, uint32_t b0, uint32_t b1) {
    asm volatile(
        "mma.sync.aligned.m16n8k16.row.col.f32.bf16.bf16.f32 "
        "{%0,%1,%2,%3}, {%4,%5,%6,%7}, {%8,%9}, {%0,%1,%2,%3};"
        : "+f"(c[0]), "+f"(c[1]), "+f"(c[2]), "+f"(c[3])
        : "r"(a[0]), "r"(a[1]), "r"(a[2]), "r"(a[3]), "r"(b0), "r"(b1));
}
#define SWZB(row, c) ((((uint32_t)(row)) << 6) + ((((uint32_t)(c) ^ (((uint32_t)(row) >> 1) & 3))) << 4))

__device__ __forceinline__ void st_unit(char* hi, char* lo, int row, int c, float4 v0, float4 v1) {
    float p0[4] = {v0.x, v0.z, v1.x, v1.z};
    float p1[4] = {v0.y, v0.w, v1.y, v1.w};
    uint32_t h[4], l[4];
#pragma unroll
    for (int j = 0; j < 4; ++j) {
        uint32_t ph = cvt2bf(p0[j], p1[j]);
        float hx = __uint_as_float(ph << 16);
        float hy = __uint_as_float(ph & 0xffff0000u);
        uint32_t pl = cvt2bf(p0[j] - hx, p1[j] - hy);
        h[j] = ph; l[j] = pl;
    }
    uint32_t off = SWZB(row, c);
    *(uint4*)(hi + off) = make_uint4(h[0], h[1], h[2], h[3]);
    *(uint4*)(lo + off) = make_uint4(l[0], l[1], l[2], l[3]);
}

// ------------------------- order (stable argsort desc) -------------------------
__global__ void compute_order_k(const int* __restrict__ xlen) {
    if (threadIdx.x == 0) {
        unsigned used = 0;
        for (int p = 0; p < 32; ++p) {
            int best = -1, bl = -2147483647;
            for (int j = 0; j < 32; ++j) {
                if (used & (1u << j)) continue;
                int L = xlen[j];
                if (L > bl) { bl = L; best = j; }
            }
            used |= (1u << best);
            d_order[p] = best;
            d_lens[p] = bl;
        }
        d_ctr2[0] = 0u;
        d_ctr2[1] = 0u;
    }
}

__global__ void bias_k(const float* __restrict__ bihf, const float* __restrict__ bhhf,
                       const float* __restrict__ bihb, const float* __restrict__ bhhb) {
    int j = blockIdx.x * 1024 + threadIdx.x;
    if (j < 1024) d_biascat[j] = bihf[j] + bhhf[j];
    else d_biascat[j] = bihb[j - 1024] + bhhb[j - 1024];
}

// weight fp32 -> bf16 hi/lo pairs
__global__ void convw_k(const float* __restrict__ src, uint16_t* __restrict__ dh,
                        uint16_t* __restrict__ dl, int npairs) {
    int i = blockIdx.x * 256 + threadIdx.x;
    if (i >= npairs) return;
    float2 v = ((const float2*)src)[i];
    uint32_t ph = cvt2bf(v.x, v.y);
    float hx = __uint_as_float(ph << 16);
    float hy = __uint_as_float(ph & 0xffff0000u);
    uint32_t pl = cvt2bf(v.x - hx, v.y - hy);
    ((uint32_t*)dh)[i] = ph;
    ((uint32_t*)dl)[i] = pl;
}

// ------------------------- fp32 GEMM (only for K=80 layer 0) -------------------------
__global__ void __launch_bounds__(256) gemm_relu_k(
    const float* __restrict__ A, const float* __restrict__ W,
    const float* __restrict__ bias, float* __restrict__ C,
    int M, int N, int K) {
    __shared__ float As[8][132];
    __shared__ float Ws[8][132];
    const int tid = threadIdx.x;
    const int n0 = blockIdx.x * 128, m0 = blockIdx.y * 128;
    const int lm = tid >> 1, lq = (tid & 1) * 4;
    const float* arow = A + (size_t)(m0 + lm) * K + lq;
    const float* wrow = W + (size_t)(n0 + lm) * K + lq;
    const int tx = tid & 15, ty = tid >> 4;
    float acc[8][8];
#pragma unroll
    for (int i = 0; i < 8; i++)
#pragma unroll
        for (int j = 0; j < 8; j++) acc[i][j] = 0.f;

    for (int k0 = 0; k0 < K; k0 += 8) {
        float4 av = *(const float4*)(arow + k0);
        float4 wv = *(const float4*)(wrow + k0);
        __syncthreads();
        As[lq + 0][lm] = av.x; As[lq + 1][lm] = av.y;
        As[lq + 2][lm] = av.z; As[lq + 3][lm] = av.w;
        Ws[lq + 0][lm] = wv.x; Ws[lq + 1][lm] = wv.y;
        Ws[lq + 2][lm] = wv.z; Ws[lq + 3][lm] = wv.w;
        __syncthreads();
#pragma unroll
        for (int k = 0; k < 8; k++) {
            float a[8], b[8];
            *(float4*)(a) = *(const float4*)&As[k][ty * 8];
            *(float4*)(a + 4) = *(const float4*)&As[k][ty * 8 + 4];
            *(float4*)(b) = *(const float4*)&Ws[k][tx * 8];
            *(float4*)(b + 4) = *(const float4*)&Ws[k][tx * 8 + 4];
#pragma unroll
            for (int i = 0; i < 8; i++)
#pragma unroll
                for (int j = 0; j < 8; j++) acc[i][j] += a[i] * b[j];
        }
    }
    float bs[8];
    *(float4*)bs = *(const float4*)&bias[n0 + tx * 8];
    *(float4*)(bs + 4) = *(const float4*)&bias[n0 + tx * 8 + 4];
#pragma unroll
    for (int i = 0; i < 8; i++) {
        float* crow = C + (size_t)(m0 + ty * 8 + i) * N + n0 + tx * 8;
        float4 v0, v1;
        v0.x = fmaxf(acc[i][0] + bs[0], 0.f);
        v0.y = fmaxf(acc[i][1] + bs[1], 0.f);
        v0.z = fmaxf(acc[i][2] + bs[2], 0.f);
        v0.w = fmaxf(acc[i][3] + bs[3], 0.f);
        v1.x = fmaxf(acc[i][4] + bs[4], 0.f);
        v1.y = fmaxf(acc[i][5] + bs[5], 0.f);
        v1.z = fmaxf(acc[i][6] + bs[6], 0.f);
        v1.w = fmaxf(acc[i][7] + bs[7], 0.f);
        *(float4*)crow = v0;
        *(float4*)(crow + 4) = v1;
    }
}

// ------------------------- HMMA split-bf16 GEMM (pre-converted B) -------------------------
template <int RELU>
__global__ void __launch_bounds__(256) gemm_mma_k(
    const float* __restrict__ A, const uint16_t* __restrict__ Bhi,
    const uint16_t* __restrict__ Blo,
    const float* __restrict__ bias, float* __restrict__ C,
    int K, int ldo) {
    extern __shared__ char smc[];
    const int tid = threadIdx.x, lane = tid & 31, wid = tid >> 5;
    const int wm = wid >> 2, wn = wid & 3;
    const int n0 = blockIdx.x * 128, m0 = blockIdx.y * 128;
    const int NCH = K >> 5;
    const uint32_t sbase = s2u(smc);
    float* sBias = (float*)(smc + 65536);
    if (tid < 128) sBias[tid] = bias[n0 + tid];

    const int ra = tid >> 2, ca = tid & 3;
    const float* Ap0 = A + (size_t)(m0 + ra) * K + ca * 8;
    const float* Ap1 = A + (size_t)(m0 + 64 + ra) * K + ca * 8;
    const int ldb = K >> 3;
    const uint4* Bh0 = (const uint4*)Bhi + (size_t)(n0 + ra) * ldb + ca;
    const uint4* Bl0 = (const uint4*)Blo + (size_t)(n0 + ra) * ldb + ca;
    const uint4* Bh1 = (const uint4*)Bhi + (size_t)(n0 + 64 + ra) * ldb + ca;
    const uint4* Bl1 = (const uint4*)Blo + (size_t)(n0 + 64 + ra) * ldb + ca;

    float acc[4][4][4];
#pragma unroll
    for (int mi = 0; mi < 4; mi++)
#pragma unroll
        for (int j = 0; j < 4; j++)
#pragma unroll
            for (int q = 0; q < 4; q++) acc[mi][j][q] = 0.f;

    {
        char* base = smc;
        st_unit(base, base + 8192, ra, ca, *(const float4*)Ap0, *(const float4*)(Ap0 + 4));
        st_unit(base, base + 8192, 64 + ra, ca, *(const float4*)Ap1, *(const float4*)(Ap1 + 4));
        uint32_t o0 = SWZB(ra, ca), o1 = SWZB(64 + ra, ca);
        *(uint4*)(base + 16384 + o0) = *Bh0;
        *(uint4*)(base + 24576 + o0) = *Bl0;
        *(uint4*)(base + 16384 + o1) = *Bh1;
        *(uint4*)(base + 24576 + o1) = *Bl1;
    }
    __syncthreads();

    for (int i = 0; i < NCH; ++i) {
        float4 pa0, pa1, pa2, pa3;
        uint4 pb0, pb1, pb2, pb3;
        const bool more = (i + 1 < NCH);
        if (more) {
            const int kc = (i + 1) << 5;
            const int ku = (i + 1) << 2;
            pa0 = *(const float4*)(Ap0 + kc); pa1 = *(const float4*)(Ap0 + kc + 4);
            pa2 = *(const float4*)(Ap1 + kc); pa3 = *(const float4*)(Ap1 + kc + 4);
            pb0 = Bh0[ku]; pb1 = Bl0[ku];
            pb2 = Bh1[ku]; pb3 = Bl1[ku];
        }
        const uint32_t ab = sbase + (i & 1) * 32768;
        const uint32_t bb = ab + 16384;
#pragma unroll
        for (int ks = 0; ks < 2; ++ks) {
            const int r = lane & 15;
            const int cu = (ks << 1) + (lane >> 4);
            uint32_t ah[4][4], al[4][4], bh[2][4], bl[2][4];
#pragma unroll
            for (int mi = 0; mi < 4; ++mi) {
                uint32_t off = SWZB(wm * 64 + mi * 16 + r, cu);
                ldsm4(ah[mi], ab + off);
                ldsm4(al[mi], ab + 8192 + off);
            }
#pragma unroll
            for (int ni = 0; ni < 2; ++ni) {
                uint32_t off = SWZB(wn * 32 + ni * 16 + r, cu);
                ldsm4(bh[ni], bb + off);
                ldsm4(bl[ni], bb + 8192 + off);
            }
#pragma unroll
            for (int mi = 0; mi < 4; ++mi)
#pragma unroll
                for (int j = 0; j < 4; ++j) {
                    const int ni = j >> 1, s = j & 1;
                    mma16816(acc[mi][j], ah[mi], bh[ni][s], bh[ni][s + 2]);
                    mma16816(acc[mi][j], al[mi], bh[ni][s], bh[ni][s + 2]);
                    mma16816(acc[mi][j], ah[mi], bl[ni][s], bl[ni][s + 2]);
                }
        }
        if (more) {
            char* base = smc + ((i + 1) & 1) * 32768;
            st_unit(base, base + 8192, ra, ca, pa0, pa1);
            st_unit(base, base + 8192, 64 + ra, ca, pa2, pa3);
            uint32_t o0 = SWZB(ra, ca), o1 = SWZB(64 + ra, ca);
            *(uint4*)(base + 16384 + o0) = pb0;
            *(uint4*)(base + 24576 + o0) = pb1;
            *(uint4*)(base + 16384 + o1) = pb2;
            *(uint4*)(base + 24576 + o1) = pb3;
        }
        __syncthreads();
    }

#pragma unroll
    for (int mi = 0; mi < 4; ++mi)
#pragma unroll
        for (int j = 0; j < 4; ++j) {
            const int row = m0 + wm * 64 + mi * 16 + (lane >> 2);
            const int colL = wn * 32 + j * 8 + (lane & 3) * 2;
            const float b0v = sBias[colL], b1v = sBias[colL + 1];
            float x0 = acc[mi][j][0] + b0v, x1 = acc[mi][j][1] + b1v;
            float x2 = acc[mi][j][2] + b0v, x3 = acc[mi][j][3] + b1v;
            if (RELU) {
                x0 = fmaxf(x0, 0.f); x1 = fmaxf(x1, 0.f);
                x2 = fmaxf(x2, 0.f); x3 = fmaxf(x3, 0.f);
            }
            *(float2*)(C + (size_t)row * ldo + n0 + colL) = make_float2(x0, x1);
            *(float2*)(C + (size_t)(row + 8) * ldo + n0 + colL) = make_float2(x2, x3);
        }
}

// ------------------------- deltas (WIN=2, edge replicate) -------------------------
__global__ void deltas_k() {
    int idx = blockIdx.x * 256 + threadIdx.x;
    if (idx >= 32 * 1024 * 64) return;
    int c4 = idx & 63, t = (idx >> 6) & 1023, b = idx >> 16;
    const float4* h4 = (const float4*)d_h;
    size_t base = (size_t)b * 65536;
    int tp1 = min(t + 1, 1023), tm1 = max(t - 1, 0);
    int tp2 = min(t + 2, 1023), tm2 = max(t - 2, 0);
    float4 a = h4[base + (size_t)tp1 * 64 + c4];
    float4 bb = h4[base + (size_t)tm1 * 64 + c4];
    float4 c = h4[base + (size_t)tp2 * 64 + c4];
    float4 d = h4[base + (size_t)tm2 * 64 + c4];
    float4 z;
    z.x = (a.x - bb.x) * 0.5f + (c.x - d.x) * 0.25f;
    z.y = (a.y - bb.y) * 0.5f + (c.y - d.y) * 0.25f;
    z.z = (a.z - bb.z) * 0.5f + (c.z - d.z) * 0.25f;
    z.w = (a.w - bb.w) * 0.5f + (c.w - d.w) * 0.25f;
    ((float4*)d_d1)[base + (size_t)t * 64 + c4] = z;
}

// ------------------------- feat assembly (sorted) -------------------------
__global__ void feat_k() {
    int idx = blockIdx.x * 256 + threadIdx.x;
    if (idx >= 32 * 1024 * 64) return;
    int c4 = idx & 63, t = (idx >> 6) & 1023, sb = idx >> 16;
    int b = d_order[sb];
    const float4* h4 = (const float4*)d_h;
    const float4* d14 = (const float4*)d_d1;
    float4* f4 = (float4*)d_feat;
    size_t base = (size_t)b * 65536;
    size_t srow = base + (size_t)t * 64 + c4;
    float4 hv = h4[srow];
    float4 d1v = d14[srow];
    int tp1 = min(t + 1, 1023), tm1 = max(t - 1, 0);
    int tp2 = min(t + 2, 1023), tm2 = max(t - 2, 0);
    float4 a = d14[base + (size_t)tp1 * 64 + c4];
    float4 bb = d14[base + (size_t)tm1 * 64 + c4];
    float4 c = d14[base + (size_t)tp2 * 64 + c4];
    float4 d = d14[base + (size_t)tm2 * 64 + c4];
    float4 d2v;
    d2v.x = (a.x - bb.x) * 0.5f + (c.x - d.x) * 0.25f;
    d2v.y = (a.y - bb.y) * 0.5f + (c.y - d.y) * 0.25f;
    d2v.z = (a.z - bb.z) * 0.5f + (c.z - d.z) * 0.25f;
    d2v.w = (a.w - bb.w) * 0.5f + (c.w - d.w) * 0.25f;
    size_t obase = ((size_t)sb * 1024 + t) * 192;
    f4[obase + c4] = hv;
    f4[obase + 64 + c4] = d1v;
    f4[obase + 128 + c4] = d2v;
}

// ------------------------- persistent bidirectional LSTM recurrence (HMMA) -------------------------
// 128 CTAs: dir = cta>>6, slice = cta&63 (16 gate rows). Per step: gate GEMM
// [32b x 16r x 256k] as split-bf16 HMMA, K split across 8 warps, smem reduce.
// smem: AH 16K | AL 16K | BH 8K | BL 8K | P 8*32*17*4 -> 66560 B
__global__ void __launch_bounds__(256, 1) lstm_rec_k(
    const float* __restrict__ Whh_f, const float* __restrict__ Whh_b,
    const float* __restrict__ h0, const float* __restrict__ c0) {
    extern __shared__ char smc[];
    const int AHOF = 0, ALOF = 16384, BHOF = 32768, BLOF = 40960, POFF = 49152;
    float* P = (float*)(smc + POFF);
    const uint32_t sb = s2u(smc);
    const int tid = threadIdx.x, lane = tid & 31, wid = tid >> 5;
    const int dir = blockIdx.x >> 6, slice = blockIdx.x & 63;
    const float* Whh = dir ? Whh_b : Whh_f;

    // stage W slice (16 rows x 256 k) as bf16 hi/lo, ldmatrix layout
    for (int i = tid; i < 4096; i += 256) {
        int r = i >> 8, k = i & 255;
        int grow = ((r >> 2) << 8) + (slice << 2) + (r & 3);
        float w = __ldg(Whh + (size_t)grow * 256 + k);
        uint32_t pk = packhl(w);
        int c = k >> 3;
        int phys = (c & 24) | ((c ^ r) & 7);
        int off = r * 512 + phys * 16 + (k & 7) * 2;
        *(uint16_t*)(smc + BHOF + off) = (uint16_t)(pk >> 16);
        *(uint16_t*)(smc + BLOF + off) = (uint16_t)(pk & 0xffffu);
    }

    const int uq = tid >> 5, ub = tid & 31;
    const int kidx = (slice << 2) + uq;
    float creg = 0.f;
    int Lb = 0;
    if (tid < 128) {
        creg = c0[(dir * 32 + ub) * 256 + kidx];
        d_Hc[0][dir][ub][kidx] = packhl(h0[(dir * 32 + ub) * 256 + kidx]);
        Lb = d_lens[ub];
    }
    __syncthreads();
    if (tid == 0)
        asm volatile("red.release.gpu.global.add.u32 [%0], %1;"
                     :: "l"(&d_ctr2[dir]), "r"(1u) : "memory");

    const int rr = lane & 15, hs = lane >> 4;

    for (int t = 0; t < 1024; ++t) {
        if (tid == 0) {
            unsigned tgt = 64u * (unsigned)(t + 1), v;
            do {
                asm volatile("ld.acquire.gpu.global.u32 %0, [%1];"
                             : "=r"(v) : "l"(&d_ctr2[dir]) : "memory");
            } while (v < tgt);
        }
        __syncthreads();
        // stage h(t): packed global -> smem bf16 hi/lo (ldmatrix layout)
        {
            const uint4* src = (const uint4*)&d_Hc[t & 1][dir][0][0];
#pragma unroll
            for (int q = 0; q < 4; ++q) {
                int p = q * 256 + tid;
                int b = p >> 5, c = p & 31;
                uint4 v0 = __ldcg(src + p * 2);
                uint4 v1 = __ldcg(src + p * 2 + 1);
                uint4 hiu, lou;
                hiu.x = __byte_perm(v0.x, v0.y, 0x7632);
                hiu.y = __byte_perm(v0.z, v0.w, 0x7632);
                hiu.z = __byte_perm(v1.x, v1.y, 0x7632);
                hiu.w = __byte_perm(v1.z, v1.w, 0x7632);
                lou.x = __byte_perm(v0.x, v0.y, 0x5410);
                lou.y = __byte_perm(v0.z, v0.w, 0x5410);
                lou.z = __byte_perm(v1.x, v1.y, 0x5410);
                lou.w = __byte_perm(v1.z, v1.w, 0x5410);
                int phys = (c & 24) | ((c ^ b) & 7);
                int off = b * 512 + phys * 16;
                *(uint4*)(smc + AHOF + off) = hiu;
                *(uint4*)(smc + ALOF + off) = lou;
            }
        }
        float zreg[4];
        if (tid < 128) {
            int tt = dir ? max(Lb - 1 - t, 0) : t;
            const float* zp = d_Z + ((size_t)ub * 1024 + tt) * 2048 + dir * 1024 + (slice << 2) + uq;
#pragma unroll
            for (int g = 0; g < 4; ++g) zreg[g] = __ldg(zp + (g << 8));
        }
        __syncthreads();
        // mma: warp wid owns k chunk wid*32
        float acc[2][2][4];
#pragma unroll
        for (int a = 0; a < 2; a++)
#pragma unroll
            for (int bq = 0; bq < 2; bq++)
#pragma unroll
                for (int q2 = 0; q2 < 4; q2++) acc[a][bq][q2] = 0.f;
        uint32_t ahr[2][2][4], alr[2][2][4], bhr[2][4], blr[2][4];
#pragma unroll
        for (int kt = 0; kt < 2; ++kt) {
            int cu = wid * 4 + kt * 2 + hs;
#pragma unroll
            for (int mt = 0; mt < 2; ++mt) {
                int row = mt * 16 + rr;
                int phys = (cu & 24) | ((cu ^ row) & 7);
                uint32_t off = (uint32_t)(row * 512 + phys * 16);
                ldsm4(ahr[mt][kt], sb + AHOF + off);
                ldsm4(alr[mt][kt], sb + ALOF + off);
            }
            {
                int row = rr;
                int phys = (cu & 24) | ((cu ^ row) & 7);
                uint32_t off = (uint32_t)(row * 512 + phys * 16);
                ldsm4(bhr[kt], sb + BHOF + off);
                ldsm4(blr[kt], sb + BLOF + off);
            }
        }
#pragma unroll
        for (int mt = 0; mt < 2; ++mt)
#pragma unroll
            for (int nt = 0; nt < 2; ++nt)
#pragma unroll
                for (int kt = 0; kt < 2; ++kt) {
                    mma16816(acc[mt][nt], ahr[mt][kt], bhr[kt][nt], bhr[kt][nt + 2]);
                    mma16816(acc[mt][nt], alr[mt][kt], bhr[kt][nt], bhr[kt][nt + 2]);
                    mma16816(acc[mt][nt], ahr[mt][kt], blr[kt][nt], blr[kt][nt + 2]);
                }
#pragma unroll
        for (int mt = 0; mt < 2; ++mt)
#pragma unroll
            for (int nt = 0; nt < 2; ++nt) {
                int b = mt * 16 + (lane >> 2);
                int r = nt * 8 + (lane & 3) * 2;
                P[(wid * 32 + b) * 17 + r] = acc[mt][nt][0];
                P[(wid * 32 + b) * 17 + r + 1] = acc[mt][nt][1];
                P[(wid * 32 + b + 8) * 17 + r] = acc[mt][nt][2];
                P[(wid * 32 + b + 8) * 17 + r + 1] = acc[mt][nt][3];
            }
        __syncthreads();
        if (tid < 128) {
            float g4[4];
#pragma unroll
            for (int g = 0; g < 4; ++g) {
                float s = zreg[g];
                int ri = 4 * g + uq;
#pragma unroll
                for (int w8 = 0; w8 < 8; ++w8) s += P[(w8 * 32 + ub) * 17 + ri];
                g4[g] = s;
            }
            float is = 1.f / (1.f + expf(-g4[0]));
            float fs = 1.f / (1.f + expf(-g4[1]));
            float gt = tanhf(g4[2]);
            float os = 1.f / (1.f + expf(-g4[3]));
            creg = fs * creg + is * gt;
            float hv = os * tanhf(creg);
            d_Hout[dir][t][kidx][ub] = hv;
            d_Hc[(t + 1) & 1][dir][ub][kidx] = packhl(hv);
        }
        __syncthreads();
        if (tid == 0)
            asm volatile("red.release.gpu.global.add.u32 [%0], %1;"
                         :: "l"(&d_ctr2[dir]), "r"(1u) : "memory");
    }
}

// ------------------------- output assembly -------------------------
__global__ void outk(float* __restrict__ out, int out_size) {
    int idx = blockIdx.x * 256 + threadIdx.x;
    if (idx >= out_size) return;
    if (idx < 16777216) {
        int j = idx & 511;
        int t = (idx >> 9) & 1023;
        int sb = idx >> 19;
        int L = d_lens[sb];
        float v = 0.f;
        if (t < L) {
            if (j < 256) v = d_Hout[0][t][j][sb];
            else v = d_Hout[1][L - 1 - t][j - 256][sb];
        }
        out[idx] = v;
    } else {
        int k = idx - 16777216;
        if (k < 32) out[idx] = (float)d_order[k];
        else out[idx] = 0.f;
    }
}

// ------------------------- launch -------------------------
extern "C" void kernel_launch(void* const* d_in, const int* in_sizes, int n_in,
                              void* d_out, int out_size) {
    const float* x = (const float*)d_in[0];
    const int* xlen = (const int*)d_in[1];
    const float* W0 = (const float*)d_in[2];
    const float* b0 = (const float*)d_in[3];
    const float* W1 = (const float*)d_in[4];
    const float* b1 = (const float*)d_in[5];
    const float* W2 = (const float*)d_in[6];
    const float* b2 = (const float*)d_in[7];
    const float* Wih_f = (const float*)d_in[8];
    const float* Whh_f = (const float*)d_in[9];
    const float* bih_f = (const float*)d_in[10];
    const float* bhh_f = (const float*)d_in[11];
    const float* Wih_b = (const float*)d_in[12];
    const float* Whh_b = (const float*)d_in[13];
    const float* bih_b = (const float*)d_in[14];
    const float* bhh_b = (const float*)d_in[15];
    const float* h0 = (const float*)d_in[16];
    const float* c0 = (const float*)d_in[17];
    float* out = (float*)d_out;

    void *p_buf0, *p_buf1, *p_h, *p_feat, *p_Z, *p_bias;
    void *p_wch, *p_wcl, *p_w1h, *p_w1l, *p_w2h, *p_w2l;
    cudaGetSymbolAddress(&p_buf0, d_buf0);
    cudaGetSymbolAddress(&p_buf1, d_buf1);
    cudaGetSymbolAddress(&p_h, d_h);
    cudaGetSymbolAddress(&p_feat, d_feat);
    cudaGetSymbolAddress(&p_Z, d_Z);
    cudaGetSymbolAddress(&p_bias, d_biascat);
    cudaGetSymbolAddress(&p_wch, d_Wch);
    cudaGetSymbolAddress(&p_wcl, d_Wcl);
    cudaGetSymbolAddress(&p_w1h, d_W1h);
    cudaGetSymbolAddress(&p_w1l, d_W1l);
    cudaGetSymbolAddress(&p_w2h, d_W2h);
    cudaGetSymbolAddress(&p_w2l, d_W2l);

    cudaFuncSetAttribute(gemm_mma_k<0>, cudaFuncAttributeMaxDynamicSharedMemorySize, 66048);
    cudaFuncSetAttribute(gemm_mma_k<1>, cudaFuncAttributeMaxDynamicSharedMemorySize, 66048);
    cudaFuncSetAttribute(lstm_rec_k, cudaFuncAttributeMaxDynamicSharedMemorySize, 66560);

    compute_order_k<<<1, 32>>>(xlen);
    bias_k<<<2, 1024>>>(bih_f, bhh_f, bih_b, bhh_b);

    // pre-convert static weights to bf16 hi/lo
    convw_k<<<(131072 + 255) / 256, 256>>>(W1, (uint16_t*)p_w1h, (uint16_t*)p_w1l, 131072);
    convw_k<<<(65536 + 255) / 256, 256>>>(W2, (uint16_t*)p_w2h, (uint16_t*)p_w2l, 65536);
    convw_k<<<(393216 + 255) / 256, 256>>>(Wih_f, (uint16_t*)p_wch, (uint16_t*)p_wcl, 393216);
    convw_k<<<(393216 + 255) / 256, 256>>>(
        Wih_b, (uint16_t*)p_wch + 1024 * 768, (uint16_t*)p_wcl + 1024 * 768, 393216);

    // encoder
    gemm_relu_k<<<dim3(4, 256), 256>>>(x, W0, b0, (float*)p_buf0, 32768, 512, 80);
    gemm_mma_k<1><<<dim3(4, 256), 256, 66048>>>(
        (const float*)p_buf0, (const uint16_t*)p_w1h, (const uint16_t*)p_w1l,
        b1, (float*)p_buf1, 512, 512);
    gemm_mma_k<1><<<dim3(2, 256), 256, 66048>>>(
        (const float*)p_buf1, (const uint16_t*)p_w2h, (const uint16_t*)p_w2l,
        b2, (float*)p_h, 512, 256);

    deltas_k<<<8192, 256>>>();
    feat_k<<<8192, 256>>>();

    // Z = feat @ [Wih_f ; Wih_b]^T + biascat  (both directions fused)
    gemm_mma_k<0><<<dim3(16, 256), 256, 66048>>>(
        (const float*)p_feat, (const uint16_t*)p_wch, (const uint16_t*)p_wcl,
        (const float*)p_bias, (float*)p_Z, 768, 2048);

    lstm_rec_k<<<128, 256, 66560>>>(Whh_f, Whh_b, h0, c0);

    outk<<<(out_size + 255) / 256, 256>>>(out, out_size);
}